// round 15
// baseline (speedup 1.0000x reference)
#include <cuda_runtime.h>
#include <cuda_fp16.h>
#include <math.h>
#include <cstdint>

// ---------------------------------------------------------------------------
// Problem constants
// ---------------------------------------------------------------------------
#define NQ     131072
#define K1P    160        // 128 feats + 3 query + pad (mult of 32)
#define HID    512

// ---------------------------------------------------------------------------
// Scratch (device globals; no cudaMalloc allowed)
// ---------------------------------------------------------------------------
__device__ __half g_planesT[3u * 64 * 64 * 128];                // fp16 channel-last planes
__device__ __half g_h0[(size_t)NQ * K1P];                       // fp16 activations
__device__ __half g_w1h[(size_t)HID * K1P];
__device__ __half g_w2h[(size_t)HID * HID];
__device__ __half g_w3h[(size_t)HID * HID];
__device__ __half g_a[(size_t)NQ * HID];
__device__ __half g_b[(size_t)NQ * HID];
__device__ float  g_part[4][(size_t)NQ];

__device__ __forceinline__ uint32_t smem_u32(const void* p) {
    uint32_t a;
    asm("{ .reg .u64 t; cvta.to.shared.u64 t, %1; cvt.u32.u64 %0, t; }" : "=r"(a) : "l"(p));
    return a;
}
__device__ __forceinline__ void cp16(uint32_t saddr, const void* g) {
    asm volatile("cp.async.cg.shared.global [%0], [%1], 16;" :: "r"(saddr), "l"(g));
}
__device__ __forceinline__ void cp_commit() {
    asm volatile("cp.async.commit_group;" ::: "memory");
}
template<int N>
__device__ __forceinline__ void cp_wait() {
    asm volatile("cp.async.wait_group %0;" :: "n"(N) : "memory");
}
__device__ __forceinline__ void ldsm4(uint32_t& r0, uint32_t& r1, uint32_t& r2, uint32_t& r3,
                                      uint32_t addr) {
    asm volatile("ldmatrix.sync.aligned.m8n8.x4.shared.b16 {%0,%1,%2,%3},[%4];"
                 : "=r"(r0), "=r"(r1), "=r"(r2), "=r"(r3) : "r"(addr));
}
__device__ __forceinline__ void mma16816(float* d, const uint32_t* a, const uint32_t* b) {
    asm volatile("mma.sync.aligned.m16n8k16.row.col.f32.f16.f16.f32 "
                 "{%0,%1,%2,%3},{%4,%5,%6,%7},{%8,%9},{%0,%1,%2,%3};"
                 : "+f"(d[0]), "+f"(d[1]), "+f"(d[2]), "+f"(d[3])
                 : "r"(a[0]), "r"(a[1]), "r"(a[2]), "r"(a[3]), "r"(b[0]), "r"(b[1]));
}
__device__ __forceinline__ uint32_t pack_h2(__half a, __half b) {
    return (uint32_t)__half_as_ushort(a) | ((uint32_t)__half_as_ushort(b) << 16);
}
// 64B-row XOR chunk swizzle: row r, 16B-chunk c (0..3) -> byte offset
__device__ __forceinline__ uint32_t swz(uint32_t r, uint32_t c) {
    return r * 64u + (((c + (r >> 1)) & 3u) * 16u);
}

// ---------------------------------------------------------------------------
// Plane transpose + fp16 convert: (3*128, 64, 64) fp32 -> (3, 4096, 128) fp16
// ---------------------------------------------------------------------------
__global__ void tplanes_kernel(const float* __restrict__ P, __half* __restrict__ out) {
    __shared__ float t[32][33];
    int b = blockIdx.x;
    int ct = b & 3;
    int yt = (b >> 2) & 127;
    int p  = b >> 9;
    int x  = threadIdx.x & 31;
    int r0 = threadIdx.x >> 5;
    int c0 = ct * 32, yx0 = yt * 32;
    #pragma unroll
    for (int cy = r0; cy < 32; cy += 8)
        t[cy][x] = P[((size_t)(p * 128 + c0 + cy)) * 4096 + yx0 + x];
    __syncthreads();
    #pragma unroll
    for (int yy = r0; yy < 32; yy += 8)
        out[((size_t)(p * 4096 + yx0 + yy)) * 128 + c0 + x] = __float2half_rn(t[x][yy]);
}

// ---------------------------------------------------------------------------
// Weight prep kernels
// ---------------------------------------------------------------------------
__global__ void prep_w1_kernel(const float* __restrict__ W1, __half* __restrict__ w1h) {
    int i = blockIdx.x * blockDim.x + threadIdx.x;
    if (i < 512 * K1P) {
        int n = i / K1P, k = i % K1P;
        w1h[i] = __float2half_rn((k < 131) ? W1[(size_t)k * 512 + n] : 0.0f);
    }
}
__global__ void prep_w_kernel(const float* __restrict__ W, __half* __restrict__ wh) {
    int i = blockIdx.x * blockDim.x + threadIdx.x;
    if (i < 512 * HID) {
        int n = i / HID, k = i % HID;
        wh[i] = __float2half_rn(W[(size_t)k * 512 + n]);
    }
}

// ---------------------------------------------------------------------------
// Sampler: warp per query; fp16 channel-last planes; one 8B LDG per corner/lane.
// ---------------------------------------------------------------------------
__global__ __launch_bounds__(256)
void sampler_kernel(const __half* __restrict__ PT, const float* __restrict__ query,
                    __half* __restrict__ h0) {
    int n = blockIdx.x * 8 + (threadIdx.x >> 5);
    int lane = threadIdx.x & 31;

    float q0 = __ldg(query + 3 * n + 0);
    float q1 = __ldg(query + 3 * n + 1);
    float q2 = __ldg(query + 3 * n + 2);

    float u[3] = { q0 / 1.1f, q1 / 1.1f, q0 / 1.1f };
    float v[3] = { q2 / 1.1f, q2 / 1.1f, q1 / 1.1f };

    float4 acc = make_float4(0.f, 0.f, 0.f, 0.f);

    #pragma unroll
    for (int p = 0; p < 3; ++p) {
        float x = (u[p] + 1.0f) * 0.5f * 63.0f;
        float y = (v[p] + 1.0f) * 0.5f * 63.0f;
        float x0f = floorf(x), y0f = floorf(y);
        float wx = x - x0f, wy = y - y0f;
        int x0 = min(max((int)x0f, 0), 63);
        int y0 = min(max((int)y0f, 0), 63);
        int x1 = min(x0 + 1, 63);
        int y1 = min(y0 + 1, 63);
        float w00 = (1.f - wx) * (1.f - wy);
        float w01 = wx * (1.f - wy);
        float w10 = (1.f - wx) * wy;
        float w11 = wx * wy;
        const __half* base = PT + (size_t)p * 4096 * 128 + lane * 4;

        auto corner = [&](int idx) -> float4 {
            uint2 raw = *(const uint2*)(base + (size_t)idx * 128);
            __half2 h01 = *reinterpret_cast<const __half2*>(&raw.x);
            __half2 h23 = *reinterpret_cast<const __half2*>(&raw.y);
            float2 lo = __half22float2(h01);
            float2 hi = __half22float2(h23);
            return make_float4(lo.x, lo.y, hi.x, hi.y);
        };
        float4 v00 = corner(y0 * 64 + x0);
        float4 v01 = corner(y0 * 64 + x1);
        float4 v10 = corner(y1 * 64 + x0);
        float4 v11 = corner(y1 * 64 + x1);
        acc.x = fmaf(w00, v00.x, fmaf(w01, v01.x, fmaf(w10, v10.x, fmaf(w11, v11.x, acc.x))));
        acc.y = fmaf(w00, v00.y, fmaf(w01, v01.y, fmaf(w10, v10.y, fmaf(w11, v11.y, acc.y))));
        acc.z = fmaf(w00, v00.z, fmaf(w01, v01.z, fmaf(w10, v10.z, fmaf(w11, v11.z, acc.z))));
        acc.w = fmaf(w00, v00.w, fmaf(w01, v01.w, fmaf(w10, v10.w, fmaf(w11, v11.w, acc.w))));
    }

    __half hv[4] = { __float2half_rn(acc.x), __float2half_rn(acc.y),
                     __float2half_rn(acc.z), __float2half_rn(acc.w) };
    size_t rb = (size_t)n * K1P;
    *(uint2*)(h0 + rb + lane * 4) = *(uint2*)hv;

    {
        int col = 128 + lane;
        float val = (lane == 0) ? q0 : (lane == 1) ? q1 : (lane == 2) ? q2 : 0.0f;
        h0[rb + col] = __float2half_rn(val);
    }
}

// ---------------------------------------------------------------------------
// Layer-1 GEMM, weight-stationary (R13): B slab 40KB resident, A ring 8 bufs.
// ---------------------------------------------------------------------------
#define NS1       5
#define B1_BYTES  (NS1 * 8192)
#define A1_RING   8
#define GSMEM1    (B1_BYTES + A1_RING * 8192)

template<int MT>
__global__ __launch_bounds__(256, 2)
void gemm1_kernel(const __half* __restrict__ A, const __half* __restrict__ Bw,
                  const float* __restrict__ bias, __half* __restrict__ C) {
    extern __shared__ char smem[];
    const int tid  = threadIdx.x;
    const int lane = tid & 31, wid = tid >> 5;
    const int n0 = blockIdx.x * 128;
    const int mbase = blockIdx.y * MT;
    const uint32_t sb = smem_u32(smem);

    const int lr0 = tid >> 2;
    const int lc0 = tid & 3;
    constexpr int TOT = MT * NS1;

    #pragma unroll
    for (int kc = 0; kc < NS1; ++kc) {
        #pragma unroll
        for (int rep = 0; rep < 2; ++rep) {
            int r = lr0 + rep * 64;
            uint32_t so = swz((uint32_t)r, (uint32_t)lc0);
            cp16(sb + kc * 8192 + so,
                 Bw + (size_t)(n0 + r) * K1P + kc * 32 + lc0 * 8);
        }
    }
    cp_commit();

    auto load_a = [&](int mt, int st, int buf) {
        uint32_t s = sb + B1_BYTES + buf * 8192;
        int m0 = (mbase + mt) * 128;
        #pragma unroll
        for (int rep = 0; rep < 2; ++rep) {
            int r = lr0 + rep * 64;
            uint32_t so = swz((uint32_t)r, (uint32_t)lc0);
            cp16(s + so, A + (size_t)(m0 + r) * K1P + st * 32 + lc0 * 8);
        }
        cp_commit();
    };

    {
        int mt = 0, st = 0;
        #pragma unroll
        for (int i = 0; i < A1_RING - 1 && i < TOT; ++i) {
            load_a(mt, st, i);
            if (++st == NS1) { st = 0; ++mt; }
        }
    }

    const int g = lane >> 3, t = lane & 7;
    const int warp_m = wid & 3, warp_n = wid >> 2;
    const uint32_t a_row  = warp_m * 32 + ((g & 1) << 3) + t;
    const uint32_t a_coff = (uint32_t)(g >> 1);
    const uint32_t b_row  = warp_n * 64 + ((g >> 1) << 3) + t;
    const uint32_t b_coff = (uint32_t)(g & 1);
    const int row_l = lane >> 2;
    const int colq  = (lane & 3) * 2;

    float acc[2][8][4];
    #pragma unroll
    for (int a = 0; a < 2; ++a)
        #pragma unroll
        for (int b = 0; b < 8; ++b)
            #pragma unroll
            for (int c = 0; c < 4; ++c) acc[a][b][c] = 0.0f;

    int nx_mt = (A1_RING - 1) / NS1;
    int nx_st = (A1_RING - 1) % NS1;
    int gst = 0;

    for (int mt_i = 0; mt_i < MT; ++mt_i) {
        #pragma unroll
        for (int st = 0; st < NS1; ++st, ++gst) {
            int ahead = TOT - 1 - gst;
            if (ahead > A1_RING - 2) ahead = A1_RING - 2;
            if      (ahead >= 6) cp_wait<6>();
            else if (ahead == 5) cp_wait<5>();
            else if (ahead == 4) cp_wait<4>();
            else if (ahead == 3) cp_wait<3>();
            else if (ahead == 2) cp_wait<2>();
            else if (ahead == 1) cp_wait<1>();
            else                 cp_wait<0>();
            __syncthreads();

            if (gst + A1_RING - 1 < TOT) {
                load_a(nx_mt, nx_st, (gst + A1_RING - 1) & (A1_RING - 1));
                if (++nx_st == NS1) { nx_st = 0; ++nx_mt; }
            }

            uint32_t sA = sb + B1_BYTES + (uint32_t)(gst & (A1_RING - 1)) * 8192;
            uint32_t sB = sb + st * 8192;
            #pragma unroll
            for (int ks = 0; ks < 2; ++ks) {
                uint32_t aF[2][4], bH[8][2];
                #pragma unroll
                for (int mt = 0; mt < 2; ++mt) {
                    uint32_t ad = sA + swz(a_row + mt * 16, (uint32_t)(ks * 2) + a_coff);
                    ldsm4(aF[mt][0], aF[mt][1], aF[mt][2], aF[mt][3], ad);
                }
                #pragma unroll
                for (int nbp = 0; nbp < 4; ++nbp) {
                    uint32_t bd = sB + swz(b_row + nbp * 16, (uint32_t)(ks * 2) + b_coff);
                    ldsm4(bH[2*nbp][0], bH[2*nbp][1], bH[2*nbp+1][0], bH[2*nbp+1][1], bd);
                }
                #pragma unroll
                for (int mt = 0; mt < 2; ++mt)
                    #pragma unroll
                    for (int nb = 0; nb < 8; ++nb)
                        mma16816(acc[mt][nb], aF[mt], bH[nb]);
            }
        }

        int m0 = (mbase + mt_i) * 128;
        #pragma unroll
        for (int mt = 0; mt < 2; ++mt) {
            int r0g = m0 + warp_m * 32 + mt * 16 + row_l;
            #pragma unroll
            for (int nb = 0; nb < 8; ++nb) {
                int c0 = n0 + warp_n * 64 + nb * 8 + colq;
                float b0 = __ldg(bias + c0), b1 = __ldg(bias + c0 + 1);
                float v0 = fmaxf(acc[mt][nb][0] + b0, 0.f);
                float v1 = fmaxf(acc[mt][nb][1] + b1, 0.f);
                float v2 = fmaxf(acc[mt][nb][2] + b0, 0.f);
                float v3 = fmaxf(acc[mt][nb][3] + b1, 0.f);
                *(uint32_t*)(C + (size_t)r0g * HID + c0) =
                    pack_h2(__float2half_rn(v0), __float2half_rn(v1));
                *(uint32_t*)(C + (size_t)(r0g + 8) * HID + c0) =
                    pack_h2(__float2half_rn(v2), __float2half_rn(v3));
            }
        }
        #pragma unroll
        for (int a = 0; a < 2; ++a)
            #pragma unroll
            for (int b = 0; b < 8; ++b)
                #pragma unroll
                for (int c = 0; c < 4; ++c) acc[a][b][c] = 0.0f;
    }
}

// ---------------------------------------------------------------------------
// Layers 2/3: weight-stationary fat CTA. 512 threads, 1 CTA/SM, 16 warps.
//   B slab 128 x 512 fp16 = 128KB resident in smem (16 chunks of 8KB).
//   A streams through 8-buffer ring (8KB stages). MT m-tiles per CTA.
//   Warp tile 32m x 32n. Ring index st&7 (16 stages/tile, static).
//   FINAL: per-slab head partials (relu * Wo) -> part[slab][m].
// ---------------------------------------------------------------------------
#define B23_BYTES (16 * 8192)                 // 131072
#define A23_RING  8
#define GSMEM23   (B23_BYTES + A23_RING * 8192)  // 196608

template<int MT, bool FINAL>
__global__ __launch_bounds__(512, 1)
void gemm23_kernel(const __half* __restrict__ A, const __half* __restrict__ Bw,
                   const float* __restrict__ bias, __half* __restrict__ C,
                   const float* __restrict__ Wo, float* __restrict__ part) {
    extern __shared__ char smem[];
    __shared__ float red[3][128];
    const int tid  = threadIdx.x;
    const int lane = tid & 31, wid = tid >> 5;      // wid 0..15
    const int n0 = blockIdx.x * 128;
    const int mbase = blockIdx.y * MT;
    const uint32_t sb = smem_u32(smem);

    const int lrow = tid >> 2;       // 0..127
    const int lchk = tid & 3;        // chunk 0..3

    // ---- stationary B: 16 k-chunks, one cp16 per thread per chunk ----
    #pragma unroll
    for (int kc = 0; kc < 16; ++kc) {
        uint32_t so = swz((uint32_t)lrow, (uint32_t)lchk);
        cp16(sb + kc * 8192 + so,
             Bw + (size_t)(n0 + lrow) * HID + kc * 32 + lchk * 8);
    }
    cp_commit();

    // ---- A stage loader ----
    auto load_a = [&](int mt, int kc, int buf) {
        int m0 = (mbase + mt) * 128;
        uint32_t so = swz((uint32_t)lrow, (uint32_t)lchk);
        cp16(sb + B23_BYTES + (uint32_t)buf * 8192 + so,
             A + (size_t)(m0 + lrow) * HID + kc * 32 + lchk * 8);
        cp_commit();
    };

    // prefetch A stages 0..6 of m-tile 0
    #pragma unroll
    for (int i = 0; i < A23_RING - 1; ++i)
        load_a(0, i, i);

    const int g = lane >> 3, t = lane & 7;
    const int warp_m = wid & 3, warp_n = wid >> 2;   // 4 x 4
    const uint32_t a_row  = warp_m * 32 + ((g & 1) << 3) + t;
    const uint32_t a_coff = (uint32_t)(g >> 1);
    const uint32_t b_row  = warp_n * 32 + ((g >> 1) << 3) + t;
    const uint32_t b_coff = (uint32_t)(g & 1);
    const int row_l = lane >> 2;
    const int colq  = (lane & 3) * 2;

    float acc[2][4][4];
    #pragma unroll
    for (int a = 0; a < 2; ++a)
        #pragma unroll
        for (int b = 0; b < 4; ++b)
            #pragma unroll
            for (int c = 0; c < 4; ++c) acc[a][b][c] = 0.0f;

    for (int mt_i = 0; mt_i < MT; ++mt_i) {
        const bool last_tile = (mt_i == MT - 1);
        #pragma unroll
        for (int st = 0; st < 16; ++st) {
            if (!last_tile) {
                cp_wait<6>();
            } else {
                int ahead = 15 - st;
                if (ahead > 6) ahead = 6;
                if      (ahead >= 6) cp_wait<6>();
                else if (ahead == 5) cp_wait<5>();
                else if (ahead == 4) cp_wait<4>();
                else if (ahead == 3) cp_wait<3>();
                else if (ahead == 2) cp_wait<2>();
                else if (ahead == 1) cp_wait<1>();
                else                 cp_wait<0>();
            }
            __syncthreads();

            // prefetch stage gst+7
            if (!last_tile || st < 9) {
                int p_mt = mt_i + ((st >= 9) ? 1 : 0);
                load_a(p_mt, (st + 7) & 15, (st + 7) & 7);
            }

            uint32_t sA = sb + B23_BYTES + (uint32_t)(st & 7) * 8192;
            uint32_t sB = sb + (uint32_t)st * 8192;
            #pragma unroll
            for (int ks = 0; ks < 2; ++ks) {
                uint32_t aF[2][4], bH[4][2];
                #pragma unroll
                for (int mt = 0; mt < 2; ++mt) {
                    uint32_t ad = sA + swz(a_row + mt * 16, (uint32_t)(ks * 2) + a_coff);
                    ldsm4(aF[mt][0], aF[mt][1], aF[mt][2], aF[mt][3], ad);
                }
                #pragma unroll
                for (int nbp = 0; nbp < 2; ++nbp) {
                    uint32_t bd = sB + swz(b_row + nbp * 16, (uint32_t)(ks * 2) + b_coff);
                    ldsm4(bH[2*nbp][0], bH[2*nbp][1], bH[2*nbp+1][0], bH[2*nbp+1][1], bd);
                }
                #pragma unroll
                for (int mt = 0; mt < 2; ++mt)
                    #pragma unroll
                    for (int nb = 0; nb < 4; ++nb)
                        mma16816(acc[mt][nb], aF[mt], bH[nb]);
            }
        }

        // ---------------- per-tile epilogue ----------------
        int m0 = (mbase + mt_i) * 128;
        if (!FINAL) {
            #pragma unroll
            for (int mt = 0; mt < 2; ++mt) {
                int r0g = m0 + warp_m * 32 + mt * 16 + row_l;
                #pragma unroll
                for (int nb = 0; nb < 4; ++nb) {
                    int c0 = n0 + warp_n * 32 + nb * 8 + colq;
                    float b0 = __ldg(bias + c0), b1 = __ldg(bias + c0 + 1);
                    float v0 = fmaxf(acc[mt][nb][0] + b0, 0.f);
                    float v1 = fmaxf(acc[mt][nb][1] + b1, 0.f);
                    float v2 = fmaxf(acc[mt][nb][2] + b0, 0.f);
                    float v3 = fmaxf(acc[mt][nb][3] + b1, 0.f);
                    *(uint32_t*)(C + (size_t)r0g * HID + c0) =
                        pack_h2(__float2half_rn(v0), __float2half_rn(v1));
                    *(uint32_t*)(C + (size_t)(r0g + 8) * HID + c0) =
                        pack_h2(__float2half_rn(v2), __float2half_rn(v3));
                }
            }
        } else {
            #pragma unroll
            for (int mt = 0; mt < 2; ++mt) {
                float p0 = 0.f, p1 = 0.f;
                #pragma unroll
                for (int nb = 0; nb < 4; ++nb) {
                    int c0 = n0 + warp_n * 32 + nb * 8 + colq;
                    float b0 = __ldg(bias + c0), b1 = __ldg(bias + c0 + 1);
                    float w0 = __ldg(Wo + c0),   w1 = __ldg(Wo + c0 + 1);
                    p0 += fmaxf(acc[mt][nb][0] + b0, 0.f) * w0
                        + fmaxf(acc[mt][nb][1] + b1, 0.f) * w1;
                    p1 += fmaxf(acc[mt][nb][2] + b0, 0.f) * w0
                        + fmaxf(acc[mt][nb][3] + b1, 0.f) * w1;
                }
                p0 += __shfl_xor_sync(0xFFFFFFFFu, p0, 1);
                p0 += __shfl_xor_sync(0xFFFFFFFFu, p0, 2);
                p1 += __shfl_xor_sync(0xFFFFFFFFu, p1, 1);
                p1 += __shfl_xor_sync(0xFFFFFFFFu, p1, 2);
                int mi = warp_m * 32 + mt * 16 + row_l;
                if ((lane & 3) == 0 && warp_n < 3) {
                    red[warp_n][mi]     = p0;
                    red[warp_n][mi + 8] = p1;
                }
                __syncthreads();
                if ((lane & 3) == 0 && warp_n == 3) {
                    part[(size_t)blockIdx.x * NQ + m0 + mi] =
                        red[0][mi] + red[1][mi] + red[2][mi] + p0;
                    part[(size_t)blockIdx.x * NQ + m0 + mi + 8] =
                        red[0][mi + 8] + red[1][mi + 8] + red[2][mi + 8] + p1;
                }
                __syncthreads();
            }
        }
        #pragma unroll
        for (int a = 0; a < 2; ++a)
            #pragma unroll
            for (int b = 0; b < 4; ++b)
                #pragma unroll
                for (int c = 0; c < 4; ++c) acc[a][b][c] = 0.0f;
    }
}

// ---------------------------------------------------------------------------
// final: out = tanh(sum of 4 slabs + bo)
// ---------------------------------------------------------------------------
__global__ void tanh_kernel(const float* __restrict__ part, const float* __restrict__ bo,
                            float* __restrict__ out) {
    int i = blockIdx.x * blockDim.x + threadIdx.x;
    if (i < NQ) {
        float s = part[i] + part[NQ + (size_t)i] + part[2 * (size_t)NQ + i] + part[3 * (size_t)NQ + i];
        out[i] = tanhf(s + __ldg(bo));
    }
}

// ---------------------------------------------------------------------------
// Launcher
// ---------------------------------------------------------------------------
#define MT1  4
#define MT23 8

extern "C" void kernel_launch(void* const* d_in, const int* in_sizes, int n_in,
                              void* d_out, int out_size) {
    const float* planes = (const float*)d_in[0];
    const float* query  = (const float*)d_in[1];
    const float* W1     = (const float*)d_in[2];
    const float* b1     = (const float*)d_in[3];
    const float* W2     = (const float*)d_in[4];
    const float* b2     = (const float*)d_in[5];
    const float* W3     = (const float*)d_in[6];
    const float* b3     = (const float*)d_in[7];
    const float* Wo     = (const float*)d_in[8];
    const float* bo     = (const float*)d_in[9];
    float* out = (float*)d_out;

    float *part;
    __half *planesT, *h0, *w1h, *w2h, *w3h, *A, *B;
    cudaGetSymbolAddress((void**)&planesT, g_planesT);
    cudaGetSymbolAddress((void**)&part, g_part);
    cudaGetSymbolAddress((void**)&h0, g_h0);
    cudaGetSymbolAddress((void**)&w1h, g_w1h);
    cudaGetSymbolAddress((void**)&w2h, g_w2h);
    cudaGetSymbolAddress((void**)&w3h, g_w3h);
    cudaGetSymbolAddress((void**)&A, g_a);
    cudaGetSymbolAddress((void**)&B, g_b);

    cudaFuncSetAttribute(gemm1_kernel<MT1>,
                         cudaFuncAttributeMaxDynamicSharedMemorySize, GSMEM1);
    cudaFuncSetAttribute(gemm23_kernel<MT23, false>,
                         cudaFuncAttributeMaxDynamicSharedMemorySize, GSMEM23);
    cudaFuncSetAttribute(gemm23_kernel<MT23, true>,
                         cudaFuncAttributeMaxDynamicSharedMemorySize, GSMEM23);

    // launch order: 1 tplanes, 2-4 prep, 5 sampler (profiled), 6 L1, 7 L2, 8 L3, 9 tanh
    tplanes_kernel<<<3 * 128 * 4, 256>>>(planes, planesT);                       // 1

    prep_w1_kernel<<<(512 * K1P + 255) / 256, 256>>>(W1, w1h);                   // 2
    prep_w_kernel<<<(512 * HID + 255) / 256, 256>>>(W2, w2h);                    // 3
    prep_w_kernel<<<(512 * HID + 255) / 256, 256>>>(W3, w3h);                    // 4

    sampler_kernel<<<NQ / 8, 256>>>(planesT, query, h0);                         // 5 <- profiled

    dim3 grid1(4, NQ / 128 / MT1);
    gemm1_kernel<MT1><<<grid1, 256, GSMEM1>>>(h0, w1h, b1, A);                   // 6

    dim3 grid23(4, NQ / 128 / MT23);
    gemm23_kernel<MT23, false><<<grid23, 512, GSMEM23>>>(                        // 7
        A, w2h, b2, B, nullptr, nullptr);
    gemm23_kernel<MT23, true><<<grid23, 512, GSMEM23>>>(                         // 8
        B, w3h, b3, nullptr, Wo, part);

    tanh_kernel<<<NQ / 256, 256>>>(part, bo, out);                               // 9
}

// round 16
// speedup vs baseline: 1.3305x; 1.3305x over previous
#include <cuda_runtime.h>
#include <cuda_fp16.h>
#include <math.h>
#include <cstdint>

// ---------------------------------------------------------------------------
// Problem constants
// ---------------------------------------------------------------------------
#define NQ     131072
#define K1P    160        // 128 feats + 3 query + pad (mult of 32)
#define HID    512

// ---------------------------------------------------------------------------
// Scratch (device globals; no cudaMalloc allowed)
// ---------------------------------------------------------------------------
__device__ __half g_planesT[3u * 64 * 64 * 128];                // fp16 channel-last planes
__device__ __half g_h0[(size_t)NQ * K1P];                       // fp16 activations
__device__ __half g_w1h[(size_t)HID * K1P];
__device__ __half g_w2h[(size_t)HID * HID];
__device__ __half g_w3h[(size_t)HID * HID];
__device__ __half g_a[(size_t)NQ * HID];
__device__ __half g_b[(size_t)NQ * HID];
__device__ float  g_part[4][(size_t)NQ];

__device__ __forceinline__ uint32_t smem_u32(const void* p) {
    uint32_t a;
    asm("{ .reg .u64 t; cvta.to.shared.u64 t, %1; cvt.u32.u64 %0, t; }" : "=r"(a) : "l"(p));
    return a;
}
__device__ __forceinline__ void cp16(uint32_t saddr, const void* g) {
    asm volatile("cp.async.cg.shared.global [%0], [%1], 16;" :: "r"(saddr), "l"(g));
}
__device__ __forceinline__ void cp_commit() {
    asm volatile("cp.async.commit_group;" ::: "memory");
}
template<int N>
__device__ __forceinline__ void cp_wait() {
    asm volatile("cp.async.wait_group %0;" :: "n"(N) : "memory");
}
__device__ __forceinline__ void ldsm4(uint32_t& r0, uint32_t& r1, uint32_t& r2, uint32_t& r3,
                                      uint32_t addr) {
    asm volatile("ldmatrix.sync.aligned.m8n8.x4.shared.b16 {%0,%1,%2,%3},[%4];"
                 : "=r"(r0), "=r"(r1), "=r"(r2), "=r"(r3) : "r"(addr));
}
__device__ __forceinline__ void mma16816(float* d, const uint32_t* a, const uint32_t* b) {
    asm volatile("mma.sync.aligned.m16n8k16.row.col.f32.f16.f16.f32 "
                 "{%0,%1,%2,%3},{%4,%5,%6,%7},{%8,%9},{%0,%1,%2,%3};"
                 : "+f"(d[0]), "+f"(d[1]), "+f"(d[2]), "+f"(d[3])
                 : "r"(a[0]), "r"(a[1]), "r"(a[2]), "r"(a[3]), "r"(b[0]), "r"(b[1]));
}
__device__ __forceinline__ uint32_t pack_h2(__half a, __half b) {
    return (uint32_t)__half_as_ushort(a) | ((uint32_t)__half_as_ushort(b) << 16);
}
// 64B-row XOR chunk swizzle: row r, 16B-chunk c (0..3) -> byte offset
__device__ __forceinline__ uint32_t swz(uint32_t r, uint32_t c) {
    return r * 64u + (((c + (r >> 1)) & 3u) * 16u);
}

// ---------------------------------------------------------------------------
// Plane transpose + fp16 convert: (3*128, 64, 64) fp32 -> (3, 4096, 128) fp16
// ---------------------------------------------------------------------------
__global__ void tplanes_kernel(const float* __restrict__ P, __half* __restrict__ out) {
    __shared__ float t[32][33];
    int b = blockIdx.x;
    int ct = b & 3;
    int yt = (b >> 2) & 127;
    int p  = b >> 9;
    int x  = threadIdx.x & 31;
    int r0 = threadIdx.x >> 5;
    int c0 = ct * 32, yx0 = yt * 32;
    #pragma unroll
    for (int cy = r0; cy < 32; cy += 8)
        t[cy][x] = P[((size_t)(p * 128 + c0 + cy)) * 4096 + yx0 + x];
    __syncthreads();
    #pragma unroll
    for (int yy = r0; yy < 32; yy += 8)
        out[((size_t)(p * 4096 + yx0 + yy)) * 128 + c0 + x] = __float2half_rn(t[x][yy]);
}

// ---------------------------------------------------------------------------
// Combined weight prep (single launch): W1 -> [512 x 160], W2/W3 -> [512 x 512]
// ---------------------------------------------------------------------------
#define PREP_N1 (512 * K1P)
#define PREP_N2 (512 * HID)
__global__ void prep_all_kernel(const float* __restrict__ W1, const float* __restrict__ W2,
                                const float* __restrict__ W3,
                                __half* __restrict__ w1h,
                                __half* __restrict__ w2h, __half* __restrict__ w3h) {
    int i = blockIdx.x * blockDim.x + threadIdx.x;
    if (i < PREP_N1) {
        int n = i / K1P, k = i % K1P;
        w1h[i] = __float2half_rn((k < 131) ? W1[(size_t)k * 512 + n] : 0.0f);
    } else if (i < PREP_N1 + PREP_N2) {
        int j = i - PREP_N1;
        int n = j / HID, k = j % HID;
        w2h[j] = __float2half_rn(W2[(size_t)k * 512 + n]);
    } else if (i < PREP_N1 + 2 * PREP_N2) {
        int j = i - PREP_N1 - PREP_N2;
        int n = j / HID, k = j % HID;
        w3h[j] = __float2half_rn(W3[(size_t)k * 512 + n]);
    }
}

// ---------------------------------------------------------------------------
// Sampler: warp per query; fp16 channel-last planes; one 8B LDG per corner/lane.
// ---------------------------------------------------------------------------
__global__ __launch_bounds__(256)
void sampler_kernel(const __half* __restrict__ PT, const float* __restrict__ query,
                    __half* __restrict__ h0) {
    int n = blockIdx.x * 8 + (threadIdx.x >> 5);
    int lane = threadIdx.x & 31;

    float q0 = __ldg(query + 3 * n + 0);
    float q1 = __ldg(query + 3 * n + 1);
    float q2 = __ldg(query + 3 * n + 2);

    float u[3] = { q0 / 1.1f, q1 / 1.1f, q0 / 1.1f };
    float v[3] = { q2 / 1.1f, q2 / 1.1f, q1 / 1.1f };

    float4 acc = make_float4(0.f, 0.f, 0.f, 0.f);

    #pragma unroll
    for (int p = 0; p < 3; ++p) {
        float x = (u[p] + 1.0f) * 0.5f * 63.0f;
        float y = (v[p] + 1.0f) * 0.5f * 63.0f;
        float x0f = floorf(x), y0f = floorf(y);
        float wx = x - x0f, wy = y - y0f;
        int x0 = min(max((int)x0f, 0), 63);
        int y0 = min(max((int)y0f, 0), 63);
        int x1 = min(x0 + 1, 63);
        int y1 = min(y0 + 1, 63);
        float w00 = (1.f - wx) * (1.f - wy);
        float w01 = wx * (1.f - wy);
        float w10 = (1.f - wx) * wy;
        float w11 = wx * wy;
        const __half* base = PT + (size_t)p * 4096 * 128 + lane * 4;

        auto corner = [&](int idx) -> float4 {
            uint2 raw = *(const uint2*)(base + (size_t)idx * 128);
            __half2 h01 = *reinterpret_cast<const __half2*>(&raw.x);
            __half2 h23 = *reinterpret_cast<const __half2*>(&raw.y);
            float2 lo = __half22float2(h01);
            float2 hi = __half22float2(h23);
            return make_float4(lo.x, lo.y, hi.x, hi.y);
        };
        float4 v00 = corner(y0 * 64 + x0);
        float4 v01 = corner(y0 * 64 + x1);
        float4 v10 = corner(y1 * 64 + x0);
        float4 v11 = corner(y1 * 64 + x1);
        acc.x = fmaf(w00, v00.x, fmaf(w01, v01.x, fmaf(w10, v10.x, fmaf(w11, v11.x, acc.x))));
        acc.y = fmaf(w00, v00.y, fmaf(w01, v01.y, fmaf(w10, v10.y, fmaf(w11, v11.y, acc.y))));
        acc.z = fmaf(w00, v00.z, fmaf(w01, v01.z, fmaf(w10, v10.z, fmaf(w11, v11.z, acc.z))));
        acc.w = fmaf(w00, v00.w, fmaf(w01, v01.w, fmaf(w10, v10.w, fmaf(w11, v11.w, acc.w))));
    }

    __half hv[4] = { __float2half_rn(acc.x), __float2half_rn(acc.y),
                     __float2half_rn(acc.z), __float2half_rn(acc.w) };
    size_t rb = (size_t)n * K1P;
    *(uint2*)(h0 + rb + lane * 4) = *(uint2*)hv;

    {
        int col = 128 + lane;
        float val = (lane == 0) ? q0 : (lane == 1) ? q1 : (lane == 2) ? q2 : 0.0f;
        h0[rb + col] = __float2half_rn(val);
    }
}

// ---------------------------------------------------------------------------
// Layer-1 GEMM, weight-stationary (R13/R14): B slab 40KB resident, A ring 8 bufs.
// CTA 128x128, BK=32, 8 warps, 2 CTAs/SM, MT m-tiles per CTA.
// ---------------------------------------------------------------------------
#define NS1       5
#define B1_BYTES  (NS1 * 8192)
#define A1_RING   8
#define GSMEM1    (B1_BYTES + A1_RING * 8192)

template<int MT>
__global__ __launch_bounds__(256, 2)
void gemm1_kernel(const __half* __restrict__ A, const __half* __restrict__ Bw,
                  const float* __restrict__ bias, __half* __restrict__ C) {
    extern __shared__ char smem[];
    const int tid  = threadIdx.x;
    const int lane = tid & 31, wid = tid >> 5;
    const int n0 = blockIdx.x * 128;
    const int mbase = blockIdx.y * MT;
    const uint32_t sb = smem_u32(smem);

    const int lr0 = tid >> 2;
    const int lc0 = tid & 3;
    constexpr int TOT = MT * NS1;

    #pragma unroll
    for (int kc = 0; kc < NS1; ++kc) {
        #pragma unroll
        for (int rep = 0; rep < 2; ++rep) {
            int r = lr0 + rep * 64;
            uint32_t so = swz((uint32_t)r, (uint32_t)lc0);
            cp16(sb + kc * 8192 + so,
                 Bw + (size_t)(n0 + r) * K1P + kc * 32 + lc0 * 8);
        }
    }
    cp_commit();

    auto load_a = [&](int mt, int st, int buf) {
        uint32_t s = sb + B1_BYTES + buf * 8192;
        int m0 = (mbase + mt) * 128;
        #pragma unroll
        for (int rep = 0; rep < 2; ++rep) {
            int r = lr0 + rep * 64;
            uint32_t so = swz((uint32_t)r, (uint32_t)lc0);
            cp16(s + so, A + (size_t)(m0 + r) * K1P + st * 32 + lc0 * 8);
        }
        cp_commit();
    };

    {
        int mt = 0, st = 0;
        #pragma unroll
        for (int i = 0; i < A1_RING - 1 && i < TOT; ++i) {
            load_a(mt, st, i);
            if (++st == NS1) { st = 0; ++mt; }
        }
    }

    const int g = lane >> 3, t = lane & 7;
    const int warp_m = wid & 3, warp_n = wid >> 2;
    const uint32_t a_row  = warp_m * 32 + ((g & 1) << 3) + t;
    const uint32_t a_coff = (uint32_t)(g >> 1);
    const uint32_t b_row  = warp_n * 64 + ((g >> 1) << 3) + t;
    const uint32_t b_coff = (uint32_t)(g & 1);
    const int row_l = lane >> 2;
    const int colq  = (lane & 3) * 2;

    float acc[2][8][4];
    #pragma unroll
    for (int a = 0; a < 2; ++a)
        #pragma unroll
        for (int b = 0; b < 8; ++b)
            #pragma unroll
            for (int c = 0; c < 4; ++c) acc[a][b][c] = 0.0f;

    int nx_mt = (A1_RING - 1) / NS1;
    int nx_st = (A1_RING - 1) % NS1;
    int gst = 0;

    for (int mt_i = 0; mt_i < MT; ++mt_i) {
        #pragma unroll
        for (int st = 0; st < NS1; ++st, ++gst) {
            int ahead = TOT - 1 - gst;
            if (ahead > A1_RING - 2) ahead = A1_RING - 2;
            if      (ahead >= 6) cp_wait<6>();
            else if (ahead == 5) cp_wait<5>();
            else if (ahead == 4) cp_wait<4>();
            else if (ahead == 3) cp_wait<3>();
            else if (ahead == 2) cp_wait<2>();
            else if (ahead == 1) cp_wait<1>();
            else                 cp_wait<0>();
            __syncthreads();

            if (gst + A1_RING - 1 < TOT) {
                load_a(nx_mt, nx_st, (gst + A1_RING - 1) & (A1_RING - 1));
                if (++nx_st == NS1) { nx_st = 0; ++nx_mt; }
            }

            uint32_t sA = sb + B1_BYTES + (uint32_t)(gst & (A1_RING - 1)) * 8192;
            uint32_t sB = sb + st * 8192;
            #pragma unroll
            for (int ks = 0; ks < 2; ++ks) {
                uint32_t aF[2][4], bH[8][2];
                #pragma unroll
                for (int mt = 0; mt < 2; ++mt) {
                    uint32_t ad = sA + swz(a_row + mt * 16, (uint32_t)(ks * 2) + a_coff);
                    ldsm4(aF[mt][0], aF[mt][1], aF[mt][2], aF[mt][3], ad);
                }
                #pragma unroll
                for (int nbp = 0; nbp < 4; ++nbp) {
                    uint32_t bd = sB + swz(b_row + nbp * 16, (uint32_t)(ks * 2) + b_coff);
                    ldsm4(bH[2*nbp][0], bH[2*nbp][1], bH[2*nbp+1][0], bH[2*nbp+1][1], bd);
                }
                #pragma unroll
                for (int mt = 0; mt < 2; ++mt)
                    #pragma unroll
                    for (int nb = 0; nb < 8; ++nb)
                        mma16816(acc[mt][nb], aF[mt], bH[nb]);
            }
        }

        int m0 = (mbase + mt_i) * 128;
        #pragma unroll
        for (int mt = 0; mt < 2; ++mt) {
            int r0g = m0 + warp_m * 32 + mt * 16 + row_l;
            #pragma unroll
            for (int nb = 0; nb < 8; ++nb) {
                int c0 = n0 + warp_n * 64 + nb * 8 + colq;
                float b0 = __ldg(bias + c0), b1 = __ldg(bias + c0 + 1);
                float v0 = fmaxf(acc[mt][nb][0] + b0, 0.f);
                float v1 = fmaxf(acc[mt][nb][1] + b1, 0.f);
                float v2 = fmaxf(acc[mt][nb][2] + b0, 0.f);
                float v3 = fmaxf(acc[mt][nb][3] + b1, 0.f);
                *(uint32_t*)(C + (size_t)r0g * HID + c0) =
                    pack_h2(__float2half_rn(v0), __float2half_rn(v1));
                *(uint32_t*)(C + (size_t)(r0g + 8) * HID + c0) =
                    pack_h2(__float2half_rn(v2), __float2half_rn(v3));
            }
        }
        #pragma unroll
        for (int a = 0; a < 2; ++a)
            #pragma unroll
            for (int b = 0; b < 8; ++b)
                #pragma unroll
                for (int c = 0; c < 4; ++c) acc[a][b][c] = 0.0f;
    }
}

// ---------------------------------------------------------------------------
// R11/R14 GEMM (layers 2/3): CTA 128x128, BK=32, 8 warps, 2 CTAs/SM,
// NBUF=6 ring (<=4 stages in flight).
// FINAL: per-slab head partials (relu * Wo) -> part[slab][m].
// ---------------------------------------------------------------------------
#define MAT_BYTES 8192
#define STAGEB    (2 * MAT_BYTES)
#define NBUF      6
#define GSMEM     (NBUF * STAGEB)

template<int K, bool FINAL>
__global__ __launch_bounds__(256, 2)
void gemm_kernel(const __half* __restrict__ A,
                 const __half* __restrict__ Bh,
                 const float* __restrict__ bias,
                 __half* __restrict__ C,
                 const float* __restrict__ Wo, float* __restrict__ part) {
    extern __shared__ char smem[];
    const int tid  = threadIdx.x;
    const int lane = tid & 31, wid = tid >> 5;
    const int m0 = blockIdx.y * 128;
    const int n0 = blockIdx.x * 128;
    const uint32_t sb = smem_u32(smem);

    const int lr0 = tid >> 2;
    const int lc0 = tid & 3;

    float acc[2][8][4];
    #pragma unroll
    for (int a = 0; a < 2; ++a)
        #pragma unroll
        for (int b = 0; b < 8; ++b)
            #pragma unroll
            for (int c = 0; c < 4; ++c) acc[a][b][c] = 0.0f;

    auto load_stage = [&](int buf, int kt) {
        uint32_t s = sb + buf * STAGEB;
        #pragma unroll
        for (int rep = 0; rep < 2; ++rep) {
            int r = lr0 + rep * 64;
            uint32_t so = swz((uint32_t)r, (uint32_t)lc0);
            size_t ga = (size_t)(m0 + r) * K + kt + lc0 * 8;
            size_t gb = (size_t)(n0 + r) * K + kt + lc0 * 8;
            cp16(s + so,             A + ga);
            cp16(s + MAT_BYTES + so, Bh + gb);
        }
        cp_commit();
    };

    constexpr int NS = K / 32;
    #pragma unroll
    for (int i = 0; i < NBUF - 1 && i < NS; ++i)
        load_stage(i, i * 32);

    const int g = lane >> 3, t = lane & 7;
    const int warp_m = wid & 3, warp_n = wid >> 2;
    const uint32_t a_row  = warp_m * 32 + ((g & 1) << 3) + t;
    const uint32_t a_coff = (uint32_t)(g >> 1);
    const uint32_t b_row  = warp_n * 64 + ((g >> 1) << 3) + t;
    const uint32_t b_coff = (uint32_t)(g & 1);

    for (int st = 0; st < NS; ++st) {
        int ahead = NS - 1 - st;
        if (ahead > NBUF - 2) ahead = NBUF - 2;
        if      (ahead >= 4) cp_wait<4>();
        else if (ahead == 3) cp_wait<3>();
        else if (ahead == 2) cp_wait<2>();
        else if (ahead == 1) cp_wait<1>();
        else                 cp_wait<0>();
        __syncthreads();

        if (st + NBUF - 1 < NS) {
            int nb = (st + NBUF - 1) % NBUF;
            load_stage(nb, (st + NBUF - 1) * 32);
        }

        uint32_t s = sb + (st % NBUF) * STAGEB;
        #pragma unroll
        for (int ks = 0; ks < 2; ++ks) {
            uint32_t aF[2][4], bH[8][2];
            #pragma unroll
            for (int mt = 0; mt < 2; ++mt) {
                uint32_t ad = s + swz(a_row + mt * 16, (uint32_t)(ks * 2) + a_coff);
                ldsm4(aF[mt][0], aF[mt][1], aF[mt][2], aF[mt][3], ad);
            }
            #pragma unroll
            for (int nbp = 0; nbp < 4; ++nbp) {
                uint32_t bd = s + MAT_BYTES + swz(b_row + nbp * 16, (uint32_t)(ks * 2) + b_coff);
                ldsm4(bH[2*nbp][0], bH[2*nbp][1], bH[2*nbp+1][0], bH[2*nbp+1][1], bd);
            }
            #pragma unroll
            for (int mt = 0; mt < 2; ++mt)
                #pragma unroll
                for (int nb = 0; nb < 8; ++nb)
                    mma16816(acc[mt][nb], aF[mt], bH[nb]);
        }
    }

    const int row_l = lane >> 2;
    const int colq  = (lane & 3) * 2;

    #pragma unroll
    for (int mt = 0; mt < 2; ++mt) {
        int r0g = m0 + warp_m * 32 + mt * 16 + row_l;
        if (!FINAL) {
            #pragma unroll
            for (int nb = 0; nb < 8; ++nb) {
                int c0 = n0 + warp_n * 64 + nb * 8 + colq;
                float b0 = __ldg(bias + c0), b1 = __ldg(bias + c0 + 1);
                float v0 = fmaxf(acc[mt][nb][0] + b0, 0.f);
                float v1 = fmaxf(acc[mt][nb][1] + b1, 0.f);
                float v2 = fmaxf(acc[mt][nb][2] + b0, 0.f);
                float v3 = fmaxf(acc[mt][nb][3] + b1, 0.f);
                *(uint32_t*)(C + (size_t)r0g * HID + c0) =
                    pack_h2(__float2half_rn(v0), __float2half_rn(v1));
                *(uint32_t*)(C + (size_t)(r0g + 8) * HID + c0) =
                    pack_h2(__float2half_rn(v2), __float2half_rn(v3));
            }
        } else {
            float p0 = 0.f, p1 = 0.f;
            #pragma unroll
            for (int nb = 0; nb < 8; ++nb) {
                int c0 = n0 + warp_n * 64 + nb * 8 + colq;
                float b0 = __ldg(bias + c0), b1 = __ldg(bias + c0 + 1);
                float w0 = __ldg(Wo + c0),   w1 = __ldg(Wo + c0 + 1);
                p0 += fmaxf(acc[mt][nb][0] + b0, 0.f) * w0
                    + fmaxf(acc[mt][nb][1] + b1, 0.f) * w1;
                p1 += fmaxf(acc[mt][nb][2] + b0, 0.f) * w0
                    + fmaxf(acc[mt][nb][3] + b1, 0.f) * w1;
            }
            p0 += __shfl_xor_sync(0xFFFFFFFFu, p0, 1);
            p0 += __shfl_xor_sync(0xFFFFFFFFu, p0, 2);
            p1 += __shfl_xor_sync(0xFFFFFFFFu, p1, 1);
            p1 += __shfl_xor_sync(0xFFFFFFFFu, p1, 2);
            __shared__ float red[128];
            if ((lane & 3) == 0) {
                int mi = warp_m * 32 + mt * 16 + row_l;
                if (warp_n == 0) { red[mi] = p0; red[mi + 8] = p1; }
            }
            __syncthreads();
            if ((lane & 3) == 0 && warp_n == 1) {
                int mi = warp_m * 32 + mt * 16 + row_l;
                part[(size_t)blockIdx.x * NQ + m0 + mi]     = red[mi] + p0;
                part[(size_t)blockIdx.x * NQ + m0 + mi + 8] = red[mi + 8] + p1;
            }
            __syncthreads();
        }
    }
}

// ---------------------------------------------------------------------------
// final: out = tanh(sum of 4 slabs + bo)
// ---------------------------------------------------------------------------
__global__ void tanh_kernel(const float* __restrict__ part, const float* __restrict__ bo,
                            float* __restrict__ out) {
    int i = blockIdx.x * blockDim.x + threadIdx.x;
    if (i < NQ) {
        float s = part[i] + part[NQ + (size_t)i] + part[2 * (size_t)NQ + i] + part[3 * (size_t)NQ + i];
        out[i] = tanhf(s + __ldg(bo));
    }
}

// ---------------------------------------------------------------------------
// Launcher
// ---------------------------------------------------------------------------
#define MT1 4

extern "C" void kernel_launch(void* const* d_in, const int* in_sizes, int n_in,
                              void* d_out, int out_size) {
    const float* planes = (const float*)d_in[0];
    const float* query  = (const float*)d_in[1];
    const float* W1     = (const float*)d_in[2];
    const float* b1     = (const float*)d_in[3];
    const float* W2     = (const float*)d_in[4];
    const float* b2     = (const float*)d_in[5];
    const float* W3     = (const float*)d_in[6];
    const float* b3     = (const float*)d_in[7];
    const float* Wo     = (const float*)d_in[8];
    const float* bo     = (const float*)d_in[9];
    float* out = (float*)d_out;

    float *part;
    __half *planesT, *h0, *w1h, *w2h, *w3h, *A, *B;
    cudaGetSymbolAddress((void**)&planesT, g_planesT);
    cudaGetSymbolAddress((void**)&part, g_part);
    cudaGetSymbolAddress((void**)&h0, g_h0);
    cudaGetSymbolAddress((void**)&w1h, g_w1h);
    cudaGetSymbolAddress((void**)&w2h, g_w2h);
    cudaGetSymbolAddress((void**)&w3h, g_w3h);
    cudaGetSymbolAddress((void**)&A, g_a);
    cudaGetSymbolAddress((void**)&B, g_b);

    cudaFuncSetAttribute(gemm1_kernel<MT1>,
                         cudaFuncAttributeMaxDynamicSharedMemorySize, GSMEM1);
    cudaFuncSetAttribute(gemm_kernel<HID, false>,
                         cudaFuncAttributeMaxDynamicSharedMemorySize, GSMEM);
    cudaFuncSetAttribute(gemm_kernel<HID, true>,
                         cudaFuncAttributeMaxDynamicSharedMemorySize, GSMEM);

    // launch order: 1 tplanes, 2 prep, 3 sampler, 4 L1, 5 L2 (profiled), 6 L3, 7 tanh
    tplanes_kernel<<<3 * 128 * 4, 256>>>(planes, planesT);                       // 1

    int prep_total = PREP_N1 + 2 * PREP_N2;
    prep_all_kernel<<<(prep_total + 255) / 256, 256>>>(W1, W2, W3,               // 2
                                                       w1h, w2h, w3h);

    sampler_kernel<<<NQ / 8, 256>>>(planesT, query, h0);                         // 3

    dim3 grid1(4, NQ / 128 / MT1);
    gemm1_kernel<MT1><<<grid1, 256, GSMEM1>>>(h0, w1h, b1, A);                   // 4

    dim3 grid(4, NQ / 128);
    gemm_kernel<HID, false><<<grid, 256, GSMEM>>>(                               // 5
        A, w2h, b2, B, nullptr, nullptr);
    gemm_kernel<HID, true><<<grid, 256, GSMEM>>>(                                // 6
        B, w3h, b3, nullptr, Wo, part);

    tanh_kernel<<<NQ / 256, 256>>>(part, bo, out);                               // 7
}

// round 17
// speedup vs baseline: 1.3359x; 1.0041x over previous
#include <cuda_runtime.h>
#include <cuda_fp16.h>
#include <math.h>
#include <cstdint>

// ---------------------------------------------------------------------------
// Problem constants
// ---------------------------------------------------------------------------
#define NQ     131072
#define K1     128        // layer-1 GEMM K: features only (query handled in epilogue)
#define HID    512

// ---------------------------------------------------------------------------
// Scratch (device globals; no cudaMalloc allowed)
// ---------------------------------------------------------------------------
__device__ __half g_planesT[3u * 64 * 64 * 128];                // fp16 channel-last planes
__device__ __half g_h0[(size_t)NQ * K1];                        // fp16 sampled features
__device__ __half g_w1h[(size_t)HID * K1];
__device__ float  g_w1q[(size_t)HID * 3];                       // rank-3 query weights (fp32)
__device__ __half g_w2h[(size_t)HID * HID];
__device__ __half g_w3h[(size_t)HID * HID];
__device__ __half g_a[(size_t)NQ * HID];
__device__ __half g_b[(size_t)NQ * HID];
__device__ float  g_part[4][(size_t)NQ];

__device__ __forceinline__ uint32_t smem_u32(const void* p) {
    uint32_t a;
    asm("{ .reg .u64 t; cvta.to.shared.u64 t, %1; cvt.u32.u64 %0, t; }" : "=r"(a) : "l"(p));
    return a;
}
__device__ __forceinline__ void cp16(uint32_t saddr, const void* g) {
    asm volatile("cp.async.cg.shared.global [%0], [%1], 16;" :: "r"(saddr), "l"(g));
}
__device__ __forceinline__ void cp_commit() {
    asm volatile("cp.async.commit_group;" ::: "memory");
}
template<int N>
__device__ __forceinline__ void cp_wait() {
    asm volatile("cp.async.wait_group %0;" :: "n"(N) : "memory");
}
__device__ __forceinline__ void ldsm4(uint32_t& r0, uint32_t& r1, uint32_t& r2, uint32_t& r3,
                                      uint32_t addr) {
    asm volatile("ldmatrix.sync.aligned.m8n8.x4.shared.b16 {%0,%1,%2,%3},[%4];"
                 : "=r"(r0), "=r"(r1), "=r"(r2), "=r"(r3) : "r"(addr));
}
__device__ __forceinline__ void mma16816(float* d, const uint32_t* a, const uint32_t* b) {
    asm volatile("mma.sync.aligned.m16n8k16.row.col.f32.f16.f16.f32 "
                 "{%0,%1,%2,%3},{%4,%5,%6,%7},{%8,%9},{%0,%1,%2,%3};"
                 : "+f"(d[0]), "+f"(d[1]), "+f"(d[2]), "+f"(d[3])
                 : "r"(a[0]), "r"(a[1]), "r"(a[2]), "r"(a[3]), "r"(b[0]), "r"(b[1]));
}
__device__ __forceinline__ uint32_t pack_h2(__half a, __half b) {
    return (uint32_t)__half_as_ushort(a) | ((uint32_t)__half_as_ushort(b) << 16);
}
// 64B-row XOR chunk swizzle: row r, 16B-chunk c (0..3) -> byte offset
__device__ __forceinline__ uint32_t swz(uint32_t r, uint32_t c) {
    return r * 64u + (((c + (r >> 1)) & 3u) * 16u);
}

// ---------------------------------------------------------------------------
// Plane transpose + fp16 convert: (3*128, 64, 64) fp32 -> (3, 4096, 128) fp16
// ---------------------------------------------------------------------------
__global__ void tplanes_kernel(const float* __restrict__ P, __half* __restrict__ out) {
    __shared__ float t[32][33];
    int b = blockIdx.x;
    int ct = b & 3;
    int yt = (b >> 2) & 127;
    int p  = b >> 9;
    int x  = threadIdx.x & 31;
    int r0 = threadIdx.x >> 5;
    int c0 = ct * 32, yx0 = yt * 32;
    #pragma unroll
    for (int cy = r0; cy < 32; cy += 8)
        t[cy][x] = P[((size_t)(p * 128 + c0 + cy)) * 4096 + yx0 + x];
    __syncthreads();
    #pragma unroll
    for (int yy = r0; yy < 32; yy += 8)
        out[((size_t)(p * 4096 + yx0 + yy)) * 128 + c0 + x] = __float2half_rn(t[x][yy]);
}

// ---------------------------------------------------------------------------
// Combined weight prep (single launch):
//   W1 feats -> w1h [512 x 128] fp16; W1 query rows -> w1q [512 x 3] fp32;
//   W2/W3 -> [512 x 512] fp16.
// ---------------------------------------------------------------------------
#define PREP_N1 (512 * K1)
#define PREP_N2 (512 * HID)
#define PREP_NQ (512 * 3)
__global__ void prep_all_kernel(const float* __restrict__ W1, const float* __restrict__ W2,
                                const float* __restrict__ W3,
                                __half* __restrict__ w1h, float* __restrict__ w1q,
                                __half* __restrict__ w2h, __half* __restrict__ w3h) {
    int i = blockIdx.x * blockDim.x + threadIdx.x;
    if (i < PREP_N1) {
        int n = i / K1, k = i % K1;
        w1h[i] = __float2half_rn(W1[(size_t)k * 512 + n]);
    } else if (i < PREP_N1 + PREP_N2) {
        int j = i - PREP_N1;
        int n = j / HID, k = j % HID;
        w2h[j] = __float2half_rn(W2[(size_t)k * 512 + n]);
    } else if (i < PREP_N1 + 2 * PREP_N2) {
        int j = i - PREP_N1 - PREP_N2;
        int n = j / HID, k = j % HID;
        w3h[j] = __float2half_rn(W3[(size_t)k * 512 + n]);
    } else if (i < PREP_N1 + 2 * PREP_N2 + PREP_NQ) {
        int j = i - PREP_N1 - 2 * PREP_N2;   // n*3 + q
        int n = j / 3, q = j % 3;
        w1q[j] = W1[(size_t)(128 + q) * 512 + n];
    }
}

// ---------------------------------------------------------------------------
// Sampler: warp per query; fp16 channel-last planes; one 8B LDG per corner/lane.
// Writes h0 [NQ x 128] features only.
// ---------------------------------------------------------------------------
__global__ __launch_bounds__(256)
void sampler_kernel(const __half* __restrict__ PT, const float* __restrict__ query,
                    __half* __restrict__ h0) {
    int n = blockIdx.x * 8 + (threadIdx.x >> 5);
    int lane = threadIdx.x & 31;

    float q0 = __ldg(query + 3 * n + 0);
    float q1 = __ldg(query + 3 * n + 1);
    float q2 = __ldg(query + 3 * n + 2);

    float u[3] = { q0 / 1.1f, q1 / 1.1f, q0 / 1.1f };
    float v[3] = { q2 / 1.1f, q2 / 1.1f, q1 / 1.1f };

    float4 acc = make_float4(0.f, 0.f, 0.f, 0.f);

    #pragma unroll
    for (int p = 0; p < 3; ++p) {
        float x = (u[p] + 1.0f) * 0.5f * 63.0f;
        float y = (v[p] + 1.0f) * 0.5f * 63.0f;
        float x0f = floorf(x), y0f = floorf(y);
        float wx = x - x0f, wy = y - y0f;
        int x0 = min(max((int)x0f, 0), 63);
        int y0 = min(max((int)y0f, 0), 63);
        int x1 = min(x0 + 1, 63);
        int y1 = min(y0 + 1, 63);
        float w00 = (1.f - wx) * (1.f - wy);
        float w01 = wx * (1.f - wy);
        float w10 = (1.f - wx) * wy;
        float w11 = wx * wy;
        const __half* base = PT + (size_t)p * 4096 * 128 + lane * 4;

        auto corner = [&](int idx) -> float4 {
            uint2 raw = *(const uint2*)(base + (size_t)idx * 128);
            __half2 h01 = *reinterpret_cast<const __half2*>(&raw.x);
            __half2 h23 = *reinterpret_cast<const __half2*>(&raw.y);
            float2 lo = __half22float2(h01);
            float2 hi = __half22float2(h23);
            return make_float4(lo.x, lo.y, hi.x, hi.y);
        };
        float4 v00 = corner(y0 * 64 + x0);
        float4 v01 = corner(y0 * 64 + x1);
        float4 v10 = corner(y1 * 64 + x0);
        float4 v11 = corner(y1 * 64 + x1);
        acc.x = fmaf(w00, v00.x, fmaf(w01, v01.x, fmaf(w10, v10.x, fmaf(w11, v11.x, acc.x))));
        acc.y = fmaf(w00, v00.y, fmaf(w01, v01.y, fmaf(w10, v10.y, fmaf(w11, v11.y, acc.y))));
        acc.z = fmaf(w00, v00.z, fmaf(w01, v01.z, fmaf(w10, v10.z, fmaf(w11, v11.z, acc.z))));
        acc.w = fmaf(w00, v00.w, fmaf(w01, v01.w, fmaf(w10, v10.w, fmaf(w11, v11.w, acc.w))));
    }

    __half hv[4] = { __float2half_rn(acc.x), __float2half_rn(acc.y),
                     __float2half_rn(acc.z), __float2half_rn(acc.w) };
    size_t rb = (size_t)n * K1;
    *(uint2*)(h0 + rb + lane * 4) = *(uint2*)hv;
}

// ---------------------------------------------------------------------------
// Layer-1 GEMM, weight-stationary, K=128 (4 stages): B slab 32KB resident,
// A ring 8 bufs. CTA 128x128, BK=32, 8 warps, 2 CTAs/SM, MT m-tiles per CTA.
// Epilogue adds exact fp32 rank-3 query term: v += q_row . w1q_col.
// ---------------------------------------------------------------------------
#define NS1       4
#define B1_BYTES  (NS1 * 8192)               // 32768
#define A1_RING   8
#define GSMEM1    (B1_BYTES + A1_RING * 8192)  // 98304

template<int MT>
__global__ __launch_bounds__(256, 2)
void gemm1_kernel(const __half* __restrict__ A, const __half* __restrict__ Bw,
                  const float* __restrict__ bias,
                  const float* __restrict__ query, const float* __restrict__ w1q,
                  __half* __restrict__ C) {
    extern __shared__ char smem[];
    const int tid  = threadIdx.x;
    const int lane = tid & 31, wid = tid >> 5;
    const int n0 = blockIdx.x * 128;
    const int mbase = blockIdx.y * MT;
    const uint32_t sb = smem_u32(smem);

    const int lr0 = tid >> 2;
    const int lc0 = tid & 3;
    constexpr int TOT = MT * NS1;

    #pragma unroll
    for (int kc = 0; kc < NS1; ++kc) {
        #pragma unroll
        for (int rep = 0; rep < 2; ++rep) {
            int r = lr0 + rep * 64;
            uint32_t so = swz((uint32_t)r, (uint32_t)lc0);
            cp16(sb + kc * 8192 + so,
                 Bw + (size_t)(n0 + r) * K1 + kc * 32 + lc0 * 8);
        }
    }
    cp_commit();

    auto load_a = [&](int mt, int st, int buf) {
        uint32_t s = sb + B1_BYTES + buf * 8192;
        int m0 = (mbase + mt) * 128;
        #pragma unroll
        for (int rep = 0; rep < 2; ++rep) {
            int r = lr0 + rep * 64;
            uint32_t so = swz((uint32_t)r, (uint32_t)lc0);
            cp16(s + so, A + (size_t)(m0 + r) * K1 + st * 32 + lc0 * 8);
        }
        cp_commit();
    };

    {
        int mt = 0, st = 0;
        #pragma unroll
        for (int i = 0; i < A1_RING - 1 && i < TOT; ++i) {
            load_a(mt, st, i);
            if (++st == NS1) { st = 0; ++mt; }
        }
    }

    const int g = lane >> 3, t = lane & 7;
    const int warp_m = wid & 3, warp_n = wid >> 2;
    const uint32_t a_row  = warp_m * 32 + ((g & 1) << 3) + t;
    const uint32_t a_coff = (uint32_t)(g >> 1);
    const uint32_t b_row  = warp_n * 64 + ((g >> 1) << 3) + t;
    const uint32_t b_coff = (uint32_t)(g & 1);
    const int row_l = lane >> 2;
    const int colq  = (lane & 3) * 2;

    float acc[2][8][4];
    #pragma unroll
    for (int a = 0; a < 2; ++a)
        #pragma unroll
        for (int b = 0; b < 8; ++b)
            #pragma unroll
            for (int c = 0; c < 4; ++c) acc[a][b][c] = 0.0f;

    int nx_mt = (A1_RING - 1) / NS1;
    int nx_st = (A1_RING - 1) % NS1;
    int gst = 0;

    for (int mt_i = 0; mt_i < MT; ++mt_i) {
        #pragma unroll
        for (int st = 0; st < NS1; ++st, ++gst) {
            int ahead = TOT - 1 - gst;
            if (ahead > A1_RING - 2) ahead = A1_RING - 2;
            if      (ahead >= 6) cp_wait<6>();
            else if (ahead == 5) cp_wait<5>();
            else if (ahead == 4) cp_wait<4>();
            else if (ahead == 3) cp_wait<3>();
            else if (ahead == 2) cp_wait<2>();
            else if (ahead == 1) cp_wait<1>();
            else                 cp_wait<0>();
            __syncthreads();

            if (gst + A1_RING - 1 < TOT) {
                load_a(nx_mt, nx_st, (gst + A1_RING - 1) & (A1_RING - 1));
                if (++nx_st == NS1) { nx_st = 0; ++nx_mt; }
            }

            uint32_t sA = sb + B1_BYTES + (uint32_t)(gst & (A1_RING - 1)) * 8192;
            uint32_t sB = sb + st * 8192;
            #pragma unroll
            for (int ks = 0; ks < 2; ++ks) {
                uint32_t aF[2][4], bH[8][2];
                #pragma unroll
                for (int mt = 0; mt < 2; ++mt) {
                    uint32_t ad = sA + swz(a_row + mt * 16, (uint32_t)(ks * 2) + a_coff);
                    ldsm4(aF[mt][0], aF[mt][1], aF[mt][2], aF[mt][3], ad);
                }
                #pragma unroll
                for (int nbp = 0; nbp < 4; ++nbp) {
                    uint32_t bd = sB + swz(b_row + nbp * 16, (uint32_t)(ks * 2) + b_coff);
                    ldsm4(bH[2*nbp][0], bH[2*nbp][1], bH[2*nbp+1][0], bH[2*nbp+1][1], bd);
                }
                #pragma unroll
                for (int mt = 0; mt < 2; ++mt)
                    #pragma unroll
                    for (int nb = 0; nb < 8; ++nb)
                        mma16816(acc[mt][nb], aF[mt], bH[nb]);
            }
        }

        // ---- per-tile epilogue with exact fp32 query correction ----
        int m0 = (mbase + mt_i) * 128;
        #pragma unroll
        for (int mt = 0; mt < 2; ++mt) {
            int r0g = m0 + warp_m * 32 + mt * 16 + row_l;
            int r1g = r0g + 8;
            float qa0 = __ldg(query + 3 * r0g),     qa1 = __ldg(query + 3 * r0g + 1),
                  qa2 = __ldg(query + 3 * r0g + 2);
            float qb0 = __ldg(query + 3 * r1g),     qb1 = __ldg(query + 3 * r1g + 1),
                  qb2 = __ldg(query + 3 * r1g + 2);
            #pragma unroll
            for (int nb = 0; nb < 8; ++nb) {
                int c0 = n0 + warp_n * 64 + nb * 8 + colq;
                float b0 = __ldg(bias + c0), b1 = __ldg(bias + c0 + 1);
                float wc00 = __ldg(w1q + c0 * 3),     wc01 = __ldg(w1q + c0 * 3 + 1),
                      wc02 = __ldg(w1q + c0 * 3 + 2);
                float wc10 = __ldg(w1q + (c0+1) * 3), wc11 = __ldg(w1q + (c0+1) * 3 + 1),
                      wc12 = __ldg(w1q + (c0+1) * 3 + 2);
                float v0 = acc[mt][nb][0] + b0 + qa0*wc00 + qa1*wc01 + qa2*wc02;
                float v1 = acc[mt][nb][1] + b1 + qa0*wc10 + qa1*wc11 + qa2*wc12;
                float v2 = acc[mt][nb][2] + b0 + qb0*wc00 + qb1*wc01 + qb2*wc02;
                float v3 = acc[mt][nb][3] + b1 + qb0*wc10 + qb1*wc11 + qb2*wc12;
                v0 = fmaxf(v0, 0.f); v1 = fmaxf(v1, 0.f);
                v2 = fmaxf(v2, 0.f); v3 = fmaxf(v3, 0.f);
                *(uint32_t*)(C + (size_t)r0g * HID + c0) =
                    pack_h2(__float2half_rn(v0), __float2half_rn(v1));
                *(uint32_t*)(C + (size_t)r1g * HID + c0) =
                    pack_h2(__float2half_rn(v2), __float2half_rn(v3));
            }
        }
        #pragma unroll
        for (int a = 0; a < 2; ++a)
            #pragma unroll
            for (int b = 0; b < 8; ++b)
                #pragma unroll
                for (int c = 0; c < 4; ++c) acc[a][b][c] = 0.0f;
    }
}

// ---------------------------------------------------------------------------
// R11/R14 GEMM (layers 2/3): CTA 128x128, BK=32, 8 warps, 2 CTAs/SM,
// NBUF=6 ring (<=4 stages in flight).
// FINAL: per-slab head partials (relu * Wo) -> part[slab][m].
// ---------------------------------------------------------------------------
#define MAT_BYTES 8192
#define STAGEB    (2 * MAT_BYTES)
#define NBUF      6
#define GSMEM     (NBUF * STAGEB)

template<int K, bool FINAL>
__global__ __launch_bounds__(256, 2)
void gemm_kernel(const __half* __restrict__ A,
                 const __half* __restrict__ Bh,
                 const float* __restrict__ bias,
                 __half* __restrict__ C,
                 const float* __restrict__ Wo, float* __restrict__ part) {
    extern __shared__ char smem[];
    const int tid  = threadIdx.x;
    const int lane = tid & 31, wid = tid >> 5;
    const int m0 = blockIdx.y * 128;
    const int n0 = blockIdx.x * 128;
    const uint32_t sb = smem_u32(smem);

    const int lr0 = tid >> 2;
    const int lc0 = tid & 3;

    float acc[2][8][4];
    #pragma unroll
    for (int a = 0; a < 2; ++a)
        #pragma unroll
        for (int b = 0; b < 8; ++b)
            #pragma unroll
            for (int c = 0; c < 4; ++c) acc[a][b][c] = 0.0f;

    auto load_stage = [&](int buf, int kt) {
        uint32_t s = sb + buf * STAGEB;
        #pragma unroll
        for (int rep = 0; rep < 2; ++rep) {
            int r = lr0 + rep * 64;
            uint32_t so = swz((uint32_t)r, (uint32_t)lc0);
            size_t ga = (size_t)(m0 + r) * K + kt + lc0 * 8;
            size_t gb = (size_t)(n0 + r) * K + kt + lc0 * 8;
            cp16(s + so,             A + ga);
            cp16(s + MAT_BYTES + so, Bh + gb);
        }
        cp_commit();
    };

    constexpr int NS = K / 32;
    #pragma unroll
    for (int i = 0; i < NBUF - 1 && i < NS; ++i)
        load_stage(i, i * 32);

    const int g = lane >> 3, t = lane & 7;
    const int warp_m = wid & 3, warp_n = wid >> 2;
    const uint32_t a_row  = warp_m * 32 + ((g & 1) << 3) + t;
    const uint32_t a_coff = (uint32_t)(g >> 1);
    const uint32_t b_row  = warp_n * 64 + ((g >> 1) << 3) + t;
    const uint32_t b_coff = (uint32_t)(g & 1);

    for (int st = 0; st < NS; ++st) {
        int ahead = NS - 1 - st;
        if (ahead > NBUF - 2) ahead = NBUF - 2;
        if      (ahead >= 4) cp_wait<4>();
        else if (ahead == 3) cp_wait<3>();
        else if (ahead == 2) cp_wait<2>();
        else if (ahead == 1) cp_wait<1>();
        else                 cp_wait<0>();
        __syncthreads();

        if (st + NBUF - 1 < NS) {
            int nb = (st + NBUF - 1) % NBUF;
            load_stage(nb, (st + NBUF - 1) * 32);
        }

        uint32_t s = sb + (st % NBUF) * STAGEB;
        #pragma unroll
        for (int ks = 0; ks < 2; ++ks) {
            uint32_t aF[2][4], bH[8][2];
            #pragma unroll
            for (int mt = 0; mt < 2; ++mt) {
                uint32_t ad = s + swz(a_row + mt * 16, (uint32_t)(ks * 2) + a_coff);
                ldsm4(aF[mt][0], aF[mt][1], aF[mt][2], aF[mt][3], ad);
            }
            #pragma unroll
            for (int nbp = 0; nbp < 4; ++nbp) {
                uint32_t bd = s + MAT_BYTES + swz(b_row + nbp * 16, (uint32_t)(ks * 2) + b_coff);
                ldsm4(bH[2*nbp][0], bH[2*nbp][1], bH[2*nbp+1][0], bH[2*nbp+1][1], bd);
            }
            #pragma unroll
            for (int mt = 0; mt < 2; ++mt)
                #pragma unroll
                for (int nb = 0; nb < 8; ++nb)
                    mma16816(acc[mt][nb], aF[mt], bH[nb]);
        }
    }

    const int row_l = lane >> 2;
    const int colq  = (lane & 3) * 2;

    #pragma unroll
    for (int mt = 0; mt < 2; ++mt) {
        int r0g = m0 + warp_m * 32 + mt * 16 + row_l;
        if (!FINAL) {
            #pragma unroll
            for (int nb = 0; nb < 8; ++nb) {
                int c0 = n0 + warp_n * 64 + nb * 8 + colq;
                float b0 = __ldg(bias + c0), b1 = __ldg(bias + c0 + 1);
                float v0 = fmaxf(acc[mt][nb][0] + b0, 0.f);
                float v1 = fmaxf(acc[mt][nb][1] + b1, 0.f);
                float v2 = fmaxf(acc[mt][nb][2] + b0, 0.f);
                float v3 = fmaxf(acc[mt][nb][3] + b1, 0.f);
                *(uint32_t*)(C + (size_t)r0g * HID + c0) =
                    pack_h2(__float2half_rn(v0), __float2half_rn(v1));
                *(uint32_t*)(C + (size_t)(r0g + 8) * HID + c0) =
                    pack_h2(__float2half_rn(v2), __float2half_rn(v3));
            }
        } else {
            float p0 = 0.f, p1 = 0.f;
            #pragma unroll
            for (int nb = 0; nb < 8; ++nb) {
                int c0 = n0 + warp_n * 64 + nb * 8 + colq;
                float b0 = __ldg(bias + c0), b1 = __ldg(bias + c0 + 1);
                float w0 = __ldg(Wo + c0),   w1 = __ldg(Wo + c0 + 1);
                p0 += fmaxf(acc[mt][nb][0] + b0, 0.f) * w0
                    + fmaxf(acc[mt][nb][1] + b1, 0.f) * w1;
                p1 += fmaxf(acc[mt][nb][2] + b0, 0.f) * w0
                    + fmaxf(acc[mt][nb][3] + b1, 0.f) * w1;
            }
            p0 += __shfl_xor_sync(0xFFFFFFFFu, p0, 1);
            p0 += __shfl_xor_sync(0xFFFFFFFFu, p0, 2);
            p1 += __shfl_xor_sync(0xFFFFFFFFu, p1, 1);
            p1 += __shfl_xor_sync(0xFFFFFFFFu, p1, 2);
            __shared__ float red[128];
            if ((lane & 3) == 0) {
                int mi = warp_m * 32 + mt * 16 + row_l;
                if (warp_n == 0) { red[mi] = p0; red[mi + 8] = p1; }
            }
            __syncthreads();
            if ((lane & 3) == 0 && warp_n == 1) {
                int mi = warp_m * 32 + mt * 16 + row_l;
                part[(size_t)blockIdx.x * NQ + m0 + mi]     = red[mi] + p0;
                part[(size_t)blockIdx.x * NQ + m0 + mi + 8] = red[mi + 8] + p1;
            }
            __syncthreads();
        }
    }
}

// ---------------------------------------------------------------------------
// final: out = tanh(sum of 4 slabs + bo)
// ---------------------------------------------------------------------------
__global__ void tanh_kernel(const float* __restrict__ part, const float* __restrict__ bo,
                            float* __restrict__ out) {
    int i = blockIdx.x * blockDim.x + threadIdx.x;
    if (i < NQ) {
        float s = part[i] + part[NQ + (size_t)i] + part[2 * (size_t)NQ + i] + part[3 * (size_t)NQ + i];
        out[i] = tanhf(s + __ldg(bo));
    }
}

// ---------------------------------------------------------------------------
// Launcher
// ---------------------------------------------------------------------------
#define MT1 4

extern "C" void kernel_launch(void* const* d_in, const int* in_sizes, int n_in,
                              void* d_out, int out_size) {
    const float* planes = (const float*)d_in[0];
    const float* query  = (const float*)d_in[1];
    const float* W1     = (const float*)d_in[2];
    const float* b1     = (const float*)d_in[3];
    const float* W2     = (const float*)d_in[4];
    const float* b2     = (const float*)d_in[5];
    const float* W3     = (const float*)d_in[6];
    const float* b3     = (const float*)d_in[7];
    const float* Wo     = (const float*)d_in[8];
    const float* bo     = (const float*)d_in[9];
    float* out = (float*)d_out;

    float *part, *w1q;
    __half *planesT, *h0, *w1h, *w2h, *w3h, *A, *B;
    cudaGetSymbolAddress((void**)&planesT, g_planesT);
    cudaGetSymbolAddress((void**)&part, g_part);
    cudaGetSymbolAddress((void**)&h0, g_h0);
    cudaGetSymbolAddress((void**)&w1h, g_w1h);
    cudaGetSymbolAddress((void**)&w1q, g_w1q);
    cudaGetSymbolAddress((void**)&w2h, g_w2h);
    cudaGetSymbolAddress((void**)&w3h, g_w3h);
    cudaGetSymbolAddress((void**)&A, g_a);
    cudaGetSymbolAddress((void**)&B, g_b);

    cudaFuncSetAttribute(gemm1_kernel<MT1>,
                         cudaFuncAttributeMaxDynamicSharedMemorySize, GSMEM1);
    cudaFuncSetAttribute(gemm_kernel<HID, false>,
                         cudaFuncAttributeMaxDynamicSharedMemorySize, GSMEM);
    cudaFuncSetAttribute(gemm_kernel<HID, true>,
                         cudaFuncAttributeMaxDynamicSharedMemorySize, GSMEM);

    // launch order: 1 tplanes, 2 prep, 3 sampler, 4 L1, 5 L2 (profiled), 6 L3, 7 tanh
    tplanes_kernel<<<3 * 128 * 4, 256>>>(planes, planesT);                       // 1

    int prep_total = PREP_N1 + 2 * PREP_N2 + PREP_NQ;
    prep_all_kernel<<<(prep_total + 255) / 256, 256>>>(W1, W2, W3,               // 2
                                                       w1h, w1q, w2h, w3h);

    sampler_kernel<<<NQ / 8, 256>>>(planesT, query, h0);                         // 3

    dim3 grid1(4, NQ / 128 / MT1);
    gemm1_kernel<MT1><<<grid1, 256, GSMEM1>>>(h0, w1h, b1, query, w1q, A);       // 4

    dim3 grid(4, NQ / 128);
    gemm_kernel<HID, false><<<grid, 256, GSMEM>>>(                               // 5
        A, w2h, b2, B, nullptr, nullptr);
    gemm_kernel<HID, true><<<grid, 256, GSMEM>>>(                                // 6
        B, w3h, b3, nullptr, Wo, part);

    tanh_kernel<<<NQ / 256, 256>>>(part, bo, out);                               // 7
}